// round 16
// baseline (speedup 1.0000x reference)
#include <cuda_runtime.h>

#define NUM_SP   1024
#define NPIX     (512 * 512)
#define NFEAT    256
#define NCLS     21
#define PAD      8
#define NBLK     64                 // sort CTAs (co-resident -> grid barrier safe)
#define PPB      (NPIX / NBLK)      // 4096 pixels per CTA
#define ITER     (PPB / 1024)       // 4 pixels per thread
#define CHUNK    64                 // pixels per gather chunk
#define MAXCPS   8                  // max chunks per segment (last chunk extends)
#define MAXCHUNK 5120               // upper bound on total chunks
#define NPERS    1184               // persistent CTAs: 148 SMs x 8

// Scratch (__device__ globals; zero-init; invariants restored every call)
__device__ unsigned g_bar;                   // monotonic grid-barrier ticket counter
__device__ unsigned g_ticket;                // chunk work queue (reset by sort_kernel)
__device__ int g_nchunks;                    // actual number of chunk slots
__device__ int g_counts[NUM_SP];
__device__ int g_offsets[NUM_SP];            // 8-padded exclusive pixel offsets
__device__ int g_blockhist[NBLK * NUM_SP];   // [blk][label]
__device__ int g_chunk_base[NUM_SP];         // first chunk slot of each segment
__device__ int g_chunk_seg[MAXCHUNK];        // packed (seg<<4)|(j<<1)|last
__device__ int g_seg_done[NUM_SP];           // arrival counters (reset by winner)
__device__ __align__(16) int   g_sorted[NPIX + PAD * NUM_SP];
__device__ __align__(16) float g_partial[MAXCHUNK * NFEAT];

// ================= Kernel 1: fused probe + hist + scan + scatter =================
// grid = NBLK(64) CTAs x 1024 threads; single software grid barrier.
__global__ void __launch_bounds__(1024) sort_kernel(const int* __restrict__ sp32) {
    __shared__ int h[NUM_SP];        // histogram, later reused as scatter bases
    __shared__ int rank_[NUM_SP];
    __shared__ int warp_sums[32];
    __shared__ int sflag;

    const int c = blockIdx.x, t = threadIdx.x;
    const int lane = t & 31, wid = t >> 5;

    h[t] = 0;
    if (t == 0) sflag = 0;
    if (c == 0 && t == 0) g_ticket = 0;          // reset chunk work queue
    __syncthreads();

    // ---- probe own window + load labels ----
    // Words [c*PPB, c*PPB+PPB) are in-bounds for BOTH int32 (NPIX words) and
    // int64 (2*NPIX words) buffers. int64 => odd words are hi-halves of values
    // in [0,1024) => all zero. int32 => odd words are random labels.
    int wreg[ITER];
    int oddnz = 0;
    #pragma unroll
    for (int k = 0; k < ITER; k++) {
        wreg[k] = sp32[c * PPB + k * 1024 + t];
        oddnz |= ((t & 1) && wreg[k] != 0) ? 1 : 0;
    }
    unsigned any = __ballot_sync(0xffffffffu, oddnz);
    if ((t & 31) == 0 && any) atomicOr(&sflag, 1);
    __syncthreads();
    const int is32 = sflag;

    int lab[ITER];
    #pragma unroll
    for (int k = 0; k < ITER; k++) {
        int s = is32 ? wreg[k] : sp32[2 * (c * PPB + k * 1024 + t)];
        lab[k] = min(max(s, 0), NUM_SP - 1);
    }

    // ---- histogram (smem atomics) ----
    #pragma unroll
    for (int k = 0; k < ITER; k++) atomicAdd(&h[lab[k]], 1);
    __syncthreads();
    g_blockhist[c * NUM_SP + t] = h[t];

    // ---- grid barrier (64 co-resident CTAs; ticket monotonic across replays) ----
    __threadfence();
    if (t == 0) {
        unsigned ticket = atomicAdd(&g_bar, 1u);
        unsigned target = (ticket / NBLK) * NBLK + NBLK;
        while (*((volatile unsigned*)&g_bar) < target) __nanosleep(64);
    }
    __syncthreads();
    __threadfence();

    // ---- redundant per-CTA scan: total count + prefix over blocks < c ----
    int cnt = 0, pre = 0;
    #pragma unroll
    for (int b0 = 0; b0 < NBLK; b0 += 8) {
        #pragma unroll
        for (int j = 0; j < 8; j++) {
            int v = g_blockhist[(b0 + j) * NUM_SP + t];
            cnt += v;
            pre += ((b0 + j) < c) ? v : 0;
        }
    }

    int cp = (cnt + PAD - 1) & ~(PAD - 1);
    int x = cp;
    #pragma unroll
    for (int off = 1; off < 32; off <<= 1) {
        int v = __shfl_up_sync(0xffffffffu, x, off);
        if (lane >= off) x += v;
    }
    if (lane == 31) warp_sums[wid] = x;
    __syncthreads();
    if (t < 32) {
        int s = warp_sums[t];
        #pragma unroll
        for (int off = 1; off < 32; off <<= 1) {
            int v = __shfl_up_sync(0xffffffffu, s, off);
            if (t >= off) s += v;
        }
        warp_sums[t] = s;
    }
    __syncthreads();
    const int excl = ((wid > 0) ? warp_sums[wid - 1] : 0) + x - cp;

    // ---- scatter (smem rank atomics; global stores only) ----
    __syncthreads();                 // done with h-as-histogram
    h[t] = excl + pre;               // this CTA's scatter base for label t
    rank_[t] = 0;
    __syncthreads();
    #pragma unroll
    for (int k = 0; k < ITER; k++) {
        int s = lab[k];
        int r = atomicAdd(&rank_[s], 1);
        g_sorted[h[s] + r] = c * PPB + k * 1024 + t;
    }

    // ---- CTA 0: publish counts/offsets + packed chunk table ----
    if (c == 0) {
        g_counts[t]  = cnt;
        g_offsets[t] = excl;
        int nch = max(1, min((cnt + CHUNK - 1) / CHUNK, MAXCPS));
        int y = nch;
        __syncthreads();             // warp_sums reuse
        #pragma unroll
        for (int off = 1; off < 32; off <<= 1) {
            int v = __shfl_up_sync(0xffffffffu, y, off);
            if (lane >= off) y += v;
        }
        if (lane == 31) warp_sums[wid] = y;
        __syncthreads();
        if (t < 32) {
            int s = warp_sums[t];
            #pragma unroll
            for (int off = 1; off < 32; off <<= 1) {
                int v = __shfl_up_sync(0xffffffffu, s, off);
                if (t >= off) s += v;
            }
            warp_sums[t] = s;
        }
        __syncthreads();
        int cexcl = ((wid > 0) ? warp_sums[wid - 1] : 0) + y - nch;
        g_chunk_base[t] = cexcl;
        for (int j = 0; j < nch; j++)
            g_chunk_seg[cexcl + j] = (t << 4) | (j << 1) | (j == nch - 1 ? 1 : 0);
        if (t == NUM_SP - 1) g_nchunks = cexcl + nch;
    }
}

// ===== Kernel 2: persistent chunk gather-sum + last-CTA combine + projection =====
// grid = NPERS CTAs; each pulls packed chunk slots from a global ticket.
__global__ void __launch_bounds__(256, 8) chunk_kernel(
    const float* __restrict__ feat,
    const float* __restrict__ w,     // (21, 256) row-major
    float* __restrict__ out)         // (1024, 21)
{
    const int tid = threadIdx.x;
    const int l   = tid & 63;
    const int g   = tid >> 6;

    const float4* __restrict__ f4 = (const float4*)feat;

    // NOTE: s_part is accessed via float4* -> MUST be 16B aligned explicitly.
    // (R15 crash: declaring slot_sh first shifted s_part to a 4B offset ->
    //  misaligned STS.128 trap.)
    __shared__ __align__(16) float s_part[4][NFEAT];
    __shared__ __align__(16) float s_nf[NFEAT];
    __shared__ int slot_sh;
    __shared__ int winner;

    const int nchunks = g_nchunks;

    for (;;) {
        if (tid == 0) slot_sh = (int)atomicAdd(&g_ticket, 1u);
        __syncthreads();
        const int slot = slot_sh;
        __syncthreads();                 // all read before next overwrite
        if (slot >= nchunks) break;

        const int e = g_chunk_seg[slot];
        const int b    = e >> 4;
        const int j    = (e >> 1) & 7;
        const int last = e & 1;

        const int start = g_offsets[b];
        const int cnt   = g_counts[b];
        const int lo    = j * CHUNK;
        const int hi    = last ? cnt : min(lo + CHUNK, cnt);

        float4 acc = make_float4(0.f, 0.f, 0.f, 0.f);

        int p = lo + g;
        for (; p + 12 < hi; p += 16) {
            int i0 = g_sorted[start + p];
            int i1 = g_sorted[start + p + 4];
            int i2 = g_sorted[start + p + 8];
            int i3 = g_sorted[start + p + 12];
            float4 v0 = __ldcs(&f4[(size_t)i0 * 64 + l]);
            float4 v1 = __ldcs(&f4[(size_t)i1 * 64 + l]);
            float4 v2 = __ldcs(&f4[(size_t)i2 * 64 + l]);
            float4 v3 = __ldcs(&f4[(size_t)i3 * 64 + l]);
            acc.x += v0.x; acc.y += v0.y; acc.z += v0.z; acc.w += v0.w;
            acc.x += v1.x; acc.y += v1.y; acc.z += v1.z; acc.w += v1.w;
            acc.x += v2.x; acc.y += v2.y; acc.z += v2.z; acc.w += v2.w;
            acc.x += v3.x; acc.y += v3.y; acc.z += v3.z; acc.w += v3.w;
        }
        for (; p < hi; p += 4) {
            int i0 = g_sorted[start + p];
            float4 v = __ldcs(&f4[(size_t)i0 * 64 + l]);
            acc.x += v.x; acc.y += v.y; acc.z += v.z; acc.w += v.w;
        }

        ((float4*)s_part[g])[l] = acc;
        __syncthreads();
        g_partial[(size_t)slot * NFEAT + tid] =
            s_part[0][tid] + s_part[1][tid] + s_part[2][tid] + s_part[3][tid];

        // ---- last-arriving chunk of this segment combines + projects ----
        const int nch = max(1, min((cnt + CHUNK - 1) / CHUNK, MAXCPS));
        __threadfence();
        if (tid == 0)
            winner = (atomicAdd(&g_seg_done[b], 1) == nch - 1) ? 1 : 0;
        __syncthreads();
        if (winner) {
            __threadfence();
            const int cb = g_chunk_base[b];
            float s = 0.f;
            for (int q = 0; q < nch; q++)            // fixed order -> deterministic
                s += g_partial[(size_t)(cb + q) * NFEAT + tid];
            s_nf[tid] = s / (float)max(cnt, 1);
            __syncthreads();

            const int wd   = tid >> 5;
            const int lane = tid & 31;
            for (int c = wd; c < NCLS; c += 8) {
                const float* __restrict__ wr = w + c * NFEAT;
                float part = 0.f;
                #pragma unroll
                for (int jj = 0; jj < 8; jj++) {
                    int f = lane + 32 * jj;
                    part += s_nf[f] * __ldg(&wr[f]);
                }
                #pragma unroll
                for (int o = 16; o > 0; o >>= 1)
                    part += __shfl_down_sync(0xffffffffu, part, o);
                if (lane == 0)
                    out[b * NCLS + c] = part;
            }
            if (tid == 0) g_seg_done[b] = 0;         // restore invariant
            __syncthreads();                         // s_nf reuse safety
        }
    }
}

extern "C" void kernel_launch(void* const* d_in, const int* in_sizes, int n_in,
                              void* d_out, int out_size) {
    const float* feat = (const float*)d_in[0];   // (1,512,512,256) f32
    const int*   sp32 = (const int*)d_in[1];     // (512,512) int32 or int64 (probed)
    const float* w    = (const float*)d_in[2];   // (21,256) f32
    float* out = (float*)d_out;                  // (1024,21) f32

    sort_kernel<<<NBLK, 1024>>>(sp32);
    chunk_kernel<<<NPERS, 256>>>(feat, w, out);
}

// round 17
// speedup vs baseline: 1.2153x; 1.2153x over previous
#include <cuda_runtime.h>

#define NUM_SP   1024
#define NPIX     (512 * 512)
#define NFEAT    256
#define NCLS     21
#define PAD      8
#define NBLK     64                 // sort CTAs (co-resident -> grid barrier safe)
#define PPB      (NPIX / NBLK)      // 4096 pixels per CTA
#define ITER     (PPB / 1024)       // 4 pixels per thread
#define CHUNK    128                // pixels per gather chunk
#define MAXCPS   8                  // max chunks per segment (last chunk extends)
#define MAXCHUNK 3072               // sum max(1,min(ceil(cnt/128),8)) <= 2048+1024

// Scratch (__device__ globals; zero-init; invariants restored every call)
__device__ unsigned g_bar;                   // monotonic grid-barrier ticket counter
__device__ int g_counts[NUM_SP];
__device__ int g_offsets[NUM_SP];            // 8-padded exclusive pixel offsets
__device__ int g_blockhist[NBLK * NUM_SP];   // [blk][label]
__device__ int g_chunk_base[NUM_SP];         // first chunk slot of each segment
__device__ int g_chunk_seg[MAXCHUNK];        // packed (seg<<4)|(j<<1)|last, -1 idle
__device__ int g_seg_done[NUM_SP];           // arrival counters (reset by winner)
__device__ __align__(16) int   g_sorted[NPIX + PAD * NUM_SP];
__device__ __align__(16) float g_partial[MAXCHUNK * NFEAT];

// ================= Kernel 1: fused probe + hist + scan + scatter =================
// grid = NBLK(64) CTAs x 1024 threads; single software grid barrier.
__global__ void __launch_bounds__(1024) sort_kernel(const int* __restrict__ sp32) {
    __shared__ int h[NUM_SP];        // histogram, later reused as scatter bases
    __shared__ int rank_[NUM_SP];
    __shared__ int warp_sums[32];
    __shared__ int sflag;

    const int c = blockIdx.x, t = threadIdx.x;
    const int lane = t & 31, wid = t >> 5;

    h[t] = 0;
    if (t == 0) sflag = 0;
    if (c == 0)                                  // clear chunk table in parallel
        for (int i = t; i < MAXCHUNK; i += 1024) g_chunk_seg[i] = -1;
    __syncthreads();

    // ---- probe own window + load labels ----
    // Words [c*PPB, c*PPB+PPB) are in-bounds for BOTH int32 (NPIX words) and
    // int64 (2*NPIX words) buffers. int64 => odd words are hi-halves of values
    // in [0,1024) => all zero. int32 => odd words are random labels.
    int wreg[ITER];
    int oddnz = 0;
    #pragma unroll
    for (int k = 0; k < ITER; k++) {
        wreg[k] = sp32[c * PPB + k * 1024 + t];
        oddnz |= ((t & 1) && wreg[k] != 0) ? 1 : 0;
    }
    unsigned any = __ballot_sync(0xffffffffu, oddnz);
    if ((t & 31) == 0 && any) atomicOr(&sflag, 1);
    __syncthreads();
    const int is32 = sflag;

    int lab[ITER];
    #pragma unroll
    for (int k = 0; k < ITER; k++) {
        int s = is32 ? wreg[k] : sp32[2 * (c * PPB + k * 1024 + t)];
        lab[k] = min(max(s, 0), NUM_SP - 1);
    }

    // ---- histogram (smem atomics) ----
    #pragma unroll
    for (int k = 0; k < ITER; k++) atomicAdd(&h[lab[k]], 1);
    __syncthreads();
    g_blockhist[c * NUM_SP + t] = h[t];

    // ---- grid barrier (64 co-resident CTAs; ticket monotonic across replays) ----
    __threadfence();
    if (t == 0) {
        unsigned ticket = atomicAdd(&g_bar, 1u);
        unsigned target = (ticket / NBLK) * NBLK + NBLK;
        while (*((volatile unsigned*)&g_bar) < target) __nanosleep(64);
    }
    __syncthreads();
    __threadfence();

    // ---- redundant per-CTA scan: total count + prefix over blocks < c ----
    int cnt = 0, pre = 0;
    #pragma unroll
    for (int b0 = 0; b0 < NBLK; b0 += 8) {
        #pragma unroll
        for (int j = 0; j < 8; j++) {
            int v = g_blockhist[(b0 + j) * NUM_SP + t];
            cnt += v;
            pre += ((b0 + j) < c) ? v : 0;
        }
    }

    int cp = (cnt + PAD - 1) & ~(PAD - 1);
    int x = cp;
    #pragma unroll
    for (int off = 1; off < 32; off <<= 1) {
        int v = __shfl_up_sync(0xffffffffu, x, off);
        if (lane >= off) x += v;
    }
    if (lane == 31) warp_sums[wid] = x;
    __syncthreads();
    if (t < 32) {
        int s = warp_sums[t];
        #pragma unroll
        for (int off = 1; off < 32; off <<= 1) {
            int v = __shfl_up_sync(0xffffffffu, s, off);
            if (t >= off) s += v;
        }
        warp_sums[t] = s;
    }
    __syncthreads();
    const int excl = ((wid > 0) ? warp_sums[wid - 1] : 0) + x - cp;

    // ---- scatter (smem rank atomics; global stores only) ----
    __syncthreads();                 // done with h-as-histogram
    h[t] = excl + pre;               // this CTA's scatter base for label t
    rank_[t] = 0;
    __syncthreads();
    #pragma unroll
    for (int k = 0; k < ITER; k++) {
        int s = lab[k];
        int r = atomicAdd(&rank_[s], 1);
        g_sorted[h[s] + r] = c * PPB + k * 1024 + t;
    }

    // ---- CTA 0: publish counts/offsets + chunk table ----
    if (c == 0) {
        g_counts[t]  = cnt;
        g_offsets[t] = excl;
        int nch = max(1, min((cnt + CHUNK - 1) / CHUNK, MAXCPS));
        int y = nch;
        __syncthreads();             // warp_sums reuse
        #pragma unroll
        for (int off = 1; off < 32; off <<= 1) {
            int v = __shfl_up_sync(0xffffffffu, y, off);
            if (lane >= off) y += v;
        }
        if (lane == 31) warp_sums[wid] = y;
        __syncthreads();
        if (t < 32) {
            int s = warp_sums[t];
            #pragma unroll
            for (int off = 1; off < 32; off <<= 1) {
                int v = __shfl_up_sync(0xffffffffu, s, off);
                if (t >= off) s += v;
            }
            warp_sums[t] = s;
        }
        __syncthreads();
        int cexcl = ((wid > 0) ? warp_sums[wid - 1] : 0) + y - nch;
        g_chunk_base[t] = cexcl;
        for (int j = 0; j < nch; j++)
            g_chunk_seg[cexcl + j] = (t << 4) | (j << 1) | (j == nch - 1 ? 1 : 0);
    }
}

// ============ Kernel 2: chunk gather-sum + last-CTA combine + projection ==========
// One CTA per 128-pixel chunk (idle slots exit immediately).
__global__ void __launch_bounds__(256, 8) chunk_kernel(
    const float* __restrict__ feat,
    const float* __restrict__ w,     // (21, 256) row-major
    float* __restrict__ out)         // (1024, 21)
{
    const int e = g_chunk_seg[blockIdx.x];
    if (e < 0) return;
    const int b    = e >> 4;
    const int j    = (e >> 1) & 7;
    const int last = e & 1;

    const int tid = threadIdx.x;
    const int l   = tid & 63;
    const int g   = tid >> 6;

    const int start = g_offsets[b];
    const int cnt   = g_counts[b];
    const int lo    = j * CHUNK;
    const int hi    = last ? cnt : min(lo + CHUNK, cnt);

    const float4* __restrict__ f4 = (const float4*)feat;

    float4 acc = make_float4(0.f, 0.f, 0.f, 0.f);

    int p = lo + g;
    for (; p + 12 < hi; p += 16) {
        int i0 = g_sorted[start + p];
        int i1 = g_sorted[start + p + 4];
        int i2 = g_sorted[start + p + 8];
        int i3 = g_sorted[start + p + 12];
        float4 v0 = __ldcs(&f4[(size_t)i0 * 64 + l]);
        float4 v1 = __ldcs(&f4[(size_t)i1 * 64 + l]);
        float4 v2 = __ldcs(&f4[(size_t)i2 * 64 + l]);
        float4 v3 = __ldcs(&f4[(size_t)i3 * 64 + l]);
        acc.x += v0.x; acc.y += v0.y; acc.z += v0.z; acc.w += v0.w;
        acc.x += v1.x; acc.y += v1.y; acc.z += v1.z; acc.w += v1.w;
        acc.x += v2.x; acc.y += v2.y; acc.z += v2.z; acc.w += v2.w;
        acc.x += v3.x; acc.y += v3.y; acc.z += v3.z; acc.w += v3.w;
    }
    for (; p < hi; p += 4) {
        int i0 = g_sorted[start + p];
        float4 v = __ldcs(&f4[(size_t)i0 * 64 + l]);
        acc.x += v.x; acc.y += v.y; acc.z += v.z; acc.w += v.w;
    }

    // 16B-aligned explicitly (R15 lesson: float4 smem access traps otherwise)
    __shared__ __align__(16) float s_part[4][NFEAT];
    __shared__ __align__(16) float s_nf[NFEAT];
    __shared__ int winner;

    ((float4*)s_part[g])[l] = acc;
    __syncthreads();
    g_partial[(size_t)blockIdx.x * NFEAT + tid] =
        s_part[0][tid] + s_part[1][tid] + s_part[2][tid] + s_part[3][tid];

    // ---- last-arriving chunk of this segment combines + projects ----
    const int nch = max(1, min((cnt + CHUNK - 1) / CHUNK, MAXCPS));
    __threadfence();
    if (tid == 0)
        winner = (atomicAdd(&g_seg_done[b], 1) == nch - 1) ? 1 : 0;
    __syncthreads();
    if (!winner) return;
    __threadfence();

    const int cb = g_chunk_base[b];
    float s = 0.f;
    for (int q = 0; q < nch; q++)                    // fixed order -> deterministic
        s += g_partial[(size_t)(cb + q) * NFEAT + tid];
    s_nf[tid] = s / (float)max(cnt, 1);
    __syncthreads();

    const int wd   = tid >> 5;
    const int lane = tid & 31;
    for (int c = wd; c < NCLS; c += 8) {
        const float* __restrict__ wr = w + c * NFEAT;
        float part = 0.f;
        #pragma unroll
        for (int jj = 0; jj < 8; jj++) {
            int f = lane + 32 * jj;
            part += s_nf[f] * __ldg(&wr[f]);
        }
        #pragma unroll
        for (int o = 16; o > 0; o >>= 1)
            part += __shfl_down_sync(0xffffffffu, part, o);
        if (lane == 0)
            out[b * NCLS + c] = part;
    }

    if (tid == 0) g_seg_done[b] = 0;                 // restore invariant
}

extern "C" void kernel_launch(void* const* d_in, const int* in_sizes, int n_in,
                              void* d_out, int out_size) {
    const float* feat = (const float*)d_in[0];   // (1,512,512,256) f32
    const int*   sp32 = (const int*)d_in[1];     // (512,512) int32 or int64 (probed)
    const float* w    = (const float*)d_in[2];   // (21,256) f32
    float* out = (float*)d_out;                  // (1024,21) f32

    sort_kernel<<<NBLK, 1024>>>(sp32);
    chunk_kernel<<<MAXCHUNK, 256>>>(feat, w, out);
}